// round 1
// baseline (speedup 1.0000x reference)
#include <cuda_runtime.h>

// Problem constants
#define T_STEPS 2000
#define BATCH   256
#define HID     16
#define SEQ     10000
#define KW      5

// Scratch: per-(t,b) precomputed gate pre-activations
//   a_x[t][b][j] = LN(xt @ Wx^T)[j]*gx[j] + bx[j] + b_gates[j]
// stored PERMUTED so that float4 at (t*256+b)*16 + m holds gates
// (j=m, j=m+16, j=m+32, j=m+48) = (i, f, g, o) for hidden index m.
__device__ float g_ax[T_STEPS * BATCH * 64];

__device__ __forceinline__ float sigf(float x) {
    return __fdividef(1.0f, 1.0f + __expf(-x));
}
__device__ __forceinline__ float tanhf_fast(float x) {
    // 2*sigmoid(2x)-1; abs err ~1e-7, safe for 2000-step recurrence
    return __fdividef(2.0f, 1.0f + __expf(-2.0f * x)) - 1.0f;
}

// ---------------------------------------------------------------------------
// Pre-pass: fully parallel over (t, b). One warp per item.
//   xt[o]  = sigmoid( b_conv[o] + sum_{k,i} Wc[o,i,k] * relu(x[b,5t+k]*Wm[i]+bm[i]) )
//   y[j]   = sum_o Wx[j,o] * xt[o]
//   a_x[j] = LN64(y)[j]*gx[j] + bx[j] + b_gates[j]    (stored permuted)
// ---------------------------------------------------------------------------
__global__ void prepass_kernel(
    const float* __restrict__ x,  const float* __restrict__ Wm,
    const float* __restrict__ bm, const float* __restrict__ Wc,
    const float* __restrict__ bconv, const float* __restrict__ Wx,
    const float* __restrict__ gx, const float* __restrict__ bx,
    const float* __restrict__ bg)
{
    __shared__ float sWm[16], sbm[16], sbc[16];
    __shared__ float sWc[16 * 16 * 5];
    __shared__ float sWx[64 * 16];
    __shared__ float sgx[64], sbx[64], sbg[64];

    for (int i = threadIdx.x; i < 16; i += blockDim.x) {
        sWm[i] = Wm[i]; sbm[i] = bm[i]; sbc[i] = bconv[i];
    }
    for (int i = threadIdx.x; i < 16 * 16 * 5; i += blockDim.x) sWc[i] = Wc[i];
    for (int i = threadIdx.x; i < 64 * 16; i += blockDim.x)     sWx[i] = Wx[i];
    for (int i = threadIdx.x; i < 64; i += blockDim.x) {
        sgx[i] = gx[i]; sbx[i] = bx[i]; sbg[i] = bg[i];
    }
    __syncthreads();

    const unsigned ALL = 0xffffffffu;
    int lane = threadIdx.x & 31;
    int warp = (blockIdx.x * blockDim.x + threadIdx.x) >> 5;
    int nw   = (gridDim.x * blockDim.x) >> 5;

    for (int item = warp; item < T_STEPS * BATCH; item += nw) {
        int t = item >> 8;       // item / 256
        int b = item & 255;      // item % 256

        // lanes 0..15 compute xt[o = lane]
        float xt = 0.0f;
        if (lane < 16) {
            float v = sbc[lane];
            #pragma unroll
            for (int k = 0; k < KW; k++) {
                float xk = __ldg(&x[b * SEQ + t * KW + k]);
                #pragma unroll
                for (int i = 0; i < 16; i++) {
                    float f = fmaxf(fmaf(xk, sWm[i], sbm[i]), 0.0f);
                    v = fmaf(sWc[lane * 80 + i * 5 + k], f, v);
                }
            }
            xt = sigf(v);
        }

        // y[j] for j = lane and j = lane+32
        float y0 = 0.0f, y1 = 0.0f;
        #pragma unroll
        for (int o = 0; o < 16; o++) {
            float xo = __shfl_sync(ALL, xt, o);
            y0 = fmaf(sWx[lane * 16 + o],        xo, y0);
            y1 = fmaf(sWx[(lane + 32) * 16 + o], xo, y1);
        }

        // LN over 64 values (2 per lane, full warp)
        float s = y0 + y1;
        float q = fmaf(y0, y0, y1 * y1);
        #pragma unroll
        for (int d = 1; d < 32; d <<= 1) {
            s += __shfl_xor_sync(ALL, s, d);
            q += __shfl_xor_sync(ALL, q, d);
        }
        float mean = s * (1.0f / 64.0f);
        float var  = fmaf(-mean, mean, q * (1.0f / 64.0f));
        float r    = rsqrtf(var + 1e-5f);

        int j0 = lane, j1 = lane + 32;
        float a0 = fmaf((y0 - mean) * r, sgx[j0], sbx[j0] + sbg[j0]);
        float a1 = fmaf((y1 - mean) * r, sgx[j1], sbx[j1] + sbg[j1]);

        // permuted store: position = (j&15)*4 + (j>>4)
        float* outp = &g_ax[item * 64];
        outp[(j0 & 15) * 4 + (j0 >> 4)] = a0;
        outp[(j1 & 15) * 4 + (j1 >> 4)] = a1;
    }
}

// ---------------------------------------------------------------------------
// Sequential LSTM scan. One warp = 2 batch rows (lanes 0-15 row A, 16-31 row B).
// Lane m owns hidden index m of its row: h[m], c[m], and all 4 of its gates.
// ---------------------------------------------------------------------------
__global__ void __launch_bounds__(32, 1) lstm_seq_kernel(
    const float* __restrict__ Wh,   const float* __restrict__ gh,
    const float* __restrict__ bh,   const float* __restrict__ gc,
    const float* __restrict__ bc,   const float* __restrict__ Wcls,
    const float* __restrict__ bcls, const float* __restrict__ h0,
    const float* __restrict__ c0,   float* __restrict__ out)
{
    const unsigned ALL = 0xffffffffu;
    int lane = threadIdx.x;
    int m    = lane & 15;
    int row  = blockIdx.x * 2 + (lane >> 4);

    // Wh rows for this lane's 4 gates (i, f, g, o)
    float w0[16], w1[16], w2[16], w3[16];
    #pragma unroll
    for (int i = 0; i < 16; i++) {
        w0[i] = Wh[(m     ) * 16 + i];
        w1[i] = Wh[(m + 16) * 16 + i];
        w2[i] = Wh[(m + 32) * 16 + i];
        w3[i] = Wh[(m + 48) * 16 + i];
    }
    float gh0 = gh[m], gh1 = gh[m + 16], gh2 = gh[m + 32], gh3 = gh[m + 48];
    float bh0 = bh[m], bh1 = bh[m + 16], bh2 = bh[m + 32], bh3 = bh[m + 48];
    float gcm = gc[m], bcm = bc[m];

    float h = h0[row * 16 + m];
    float c = c0[row * 16 + m];

    const float4* ax = (const float4*)g_ax;
    const int stride = BATCH * 16;               // float4s per timestep
    int base = row * 16 + m;

    // 2-deep prefetch to hide DRAM latency (~580 cyc > ~450 cyc step time)
    float4 buf0 = ax[base];
    float4 buf1 = ax[base + stride];

    for (int t = 0; t < T_STEPS; t++) {
        float4 cur = buf0;
        buf0 = buf1;
        if (t + 2 < T_STEPS)
            buf1 = ax[base + (t + 2) * stride];

        // h @ Wh^T for this lane's 4 gate rows (width-16 shuffle broadcast of h)
        float y0 = 0.0f, y1 = 0.0f, y2 = 0.0f, y3 = 0.0f;
        #pragma unroll
        for (int i = 0; i < 16; i++) {
            float hi = __shfl_sync(ALL, h, i, 16);
            y0 = fmaf(w0[i], hi, y0);
            y1 = fmaf(w1[i], hi, y1);
            y2 = fmaf(w2[i], hi, y2);
            y3 = fmaf(w3[i], hi, y3);
        }

        // LN over the 64 gate pre-activations of this row (4/lane, 16 lanes)
        float s = (y0 + y1) + (y2 + y3);
        float q = fmaf(y0, y0, fmaf(y1, y1, fmaf(y2, y2, y3 * y3)));
        #pragma unroll
        for (int d = 1; d < 16; d <<= 1) {
            s += __shfl_xor_sync(ALL, s, d);
            q += __shfl_xor_sync(ALL, q, d);
        }
        float mean = s * (1.0f / 64.0f);
        float var  = fmaf(-mean, mean, q * (1.0f / 64.0f));
        float r    = rsqrtf(var + 1e-5f);

        float gi = fmaf((y0 - mean) * r, gh0, bh0) + cur.x;
        float gf = fmaf((y1 - mean) * r, gh1, bh1) + cur.y;
        float gg = fmaf((y2 - mean) * r, gh2, bh2) + cur.z;
        float go = fmaf((y3 - mean) * r, gh3, bh3) + cur.w;

        float ig = sigf(gi);
        float fg = sigf(gf);
        float gt = tanhf_fast(gg);
        float og = sigf(go);

        c = fmaf(fg, c, ig * gt);

        // LN over the 16 c values of this row
        float sc = c, qc = c * c;
        #pragma unroll
        for (int d = 1; d < 16; d <<= 1) {
            sc += __shfl_xor_sync(ALL, sc, d);
            qc += __shfl_xor_sync(ALL, qc, d);
        }
        float mc = sc * (1.0f / 16.0f);
        float vc = fmaf(-mc, mc, qc * (1.0f / 16.0f));
        float rc = rsqrtf(vc + 1e-5f);
        float cn = fmaf((c - mc) * rc, gcm, bcm);

        h = og * tanhf_fast(cn);
    }

    // classifier: sigmoid(h . W_cls + b_cls)
    float v = h * Wcls[m];
    #pragma unroll
    for (int d = 1; d < 16; d <<= 1)
        v += __shfl_xor_sync(ALL, v, d);
    if (m == 0)
        out[row] = sigf(v + bcls[0]);
}

// ---------------------------------------------------------------------------
extern "C" void kernel_launch(void* const* d_in, const int* in_sizes, int n_in,
                              void* d_out, int out_size)
{
    const float* x     = (const float*)d_in[0];
    const float* Wm    = (const float*)d_in[1];
    const float* bm    = (const float*)d_in[2];
    const float* Wc    = (const float*)d_in[3];
    const float* bconv = (const float*)d_in[4];
    const float* Wx    = (const float*)d_in[5];
    const float* Wh    = (const float*)d_in[6];
    const float* bg    = (const float*)d_in[7];
    const float* gx    = (const float*)d_in[8];
    const float* bx    = (const float*)d_in[9];
    const float* gh    = (const float*)d_in[10];
    const float* bh    = (const float*)d_in[11];
    const float* gc    = (const float*)d_in[12];
    const float* bc    = (const float*)d_in[13];
    const float* Wcls  = (const float*)d_in[14];
    const float* bcls  = (const float*)d_in[15];
    const float* h0    = (const float*)d_in[16];
    const float* c0    = (const float*)d_in[17];
    float* out = (float*)d_out;

    prepass_kernel<<<2048, 256>>>(x, Wm, bm, Wc, bconv, Wx, gx, bx, bg);
    lstm_seq_kernel<<<BATCH / 2, 32>>>(Wh, gh, bh, gc, bc, Wcls, bcls, h0, c0, out);
}

// round 2
// speedup vs baseline: 1.6001x; 1.6001x over previous
#include <cuda_runtime.h>

#define T_STEPS 2000
#define BATCH   256
#define SEQ     10000
#define KW      5

// Gate pre-activations a_x[t][b][j] = LN64(xt@Wx^T)[j]*gx[j] + bx[j] + b_gates[j],
// stored so that float2 at (t*256+b)*32 + l = { a[j=l], a[j=l+32] }.
// Scan lane l (0..31) then owns gates (i|f)[l&15] and (g|o)[l&15].
__device__ float g_ax[(size_t)T_STEPS * BATCH * 64];

__device__ __forceinline__ float sigf(float x) {
    return __fdividef(1.0f, 1.0f + __expf(-x));
}

// ---------------------------------------------------------------------------
// Pre-pass: one THREAD per (t, b) item. All 64 LN values live in registers:
// no shuffles, no cross-thread traffic. Weights in smem, transposed so the
// inner loops vectorize to LDS.128 broadcasts.
// ---------------------------------------------------------------------------
__global__ void __launch_bounds__(256) prepass_kernel(
    const float* __restrict__ x,  const float* __restrict__ Wm,
    const float* __restrict__ bm, const float* __restrict__ Wc,
    const float* __restrict__ bconv, const float* __restrict__ Wx,
    const float* __restrict__ gx, const float* __restrict__ bx,
    const float* __restrict__ bg)
{
    __shared__ float sWm[16], sbm[16], sbc[16];
    __shared__ float sWcT[80 * 16];   // [(i*5+k)][o]  (transposed conv weights)
    __shared__ float sWxT[16 * 64];   // [o][j]        (transposed Wx)
    __shared__ float sgx[64], sbxg[64];

    for (int idx = threadIdx.x; idx < 16; idx += blockDim.x) {
        sWm[idx] = Wm[idx]; sbm[idx] = bm[idx]; sbc[idx] = bconv[idx];
    }
    for (int idx = threadIdx.x; idx < 80 * 16; idx += blockDim.x) {
        int ik = idx >> 4, o = idx & 15;           // ik = i*5+k
        sWcT[idx] = Wc[o * 80 + ik];
    }
    for (int idx = threadIdx.x; idx < 16 * 64; idx += blockDim.x) {
        int o = idx >> 6, j = idx & 63;
        sWxT[idx] = Wx[j * 16 + o];
    }
    for (int idx = threadIdx.x; idx < 64; idx += blockDim.x) {
        sgx[idx] = gx[idx]; sbxg[idx] = bx[idx] + bg[idx];
    }
    __syncthreads();

    int item = blockIdx.x * blockDim.x + threadIdx.x;   // item = t*256 + b
    if (item >= T_STEPS * BATCH) return;
    int t = item >> 8;
    int b = item & 255;

    // conv + relu-MLP fused: xt[o] = sigmoid(bc[o] + sum_{k,i} Wc[o,i,k]*relu(x_k*Wm_i+bm_i))
    float xt[16];
    #pragma unroll
    for (int o = 0; o < 16; o++) xt[o] = sbc[o];

    #pragma unroll
    for (int k = 0; k < KW; k++) {
        float xk = __ldg(&x[b * SEQ + t * KW + k]);
        #pragma unroll
        for (int i = 0; i < 16; i++) {
            float f = fmaxf(fmaf(xk, sWm[i], sbm[i]), 0.0f);
            const float4* wr = (const float4*)&sWcT[(i * KW + k) * 16];
            #pragma unroll
            for (int o4 = 0; o4 < 4; o4++) {
                float4 w = wr[o4];
                xt[o4 * 4 + 0] = fmaf(w.x, f, xt[o4 * 4 + 0]);
                xt[o4 * 4 + 1] = fmaf(w.y, f, xt[o4 * 4 + 1]);
                xt[o4 * 4 + 2] = fmaf(w.z, f, xt[o4 * 4 + 2]);
                xt[o4 * 4 + 3] = fmaf(w.w, f, xt[o4 * 4 + 3]);
            }
        }
    }
    #pragma unroll
    for (int o = 0; o < 16; o++) xt[o] = sigf(xt[o]);

    // y = xt @ Wx^T  (64 outputs, register-resident)
    float y[64];
    #pragma unroll
    for (int j = 0; j < 64; j++) y[j] = 0.0f;
    #pragma unroll
    for (int o = 0; o < 16; o++) {
        float xo = xt[o];
        const float4* wr = (const float4*)&sWxT[o * 64];
        #pragma unroll
        for (int j4 = 0; j4 < 16; j4++) {
            float4 w = wr[j4];
            y[j4 * 4 + 0] = fmaf(w.x, xo, y[j4 * 4 + 0]);
            y[j4 * 4 + 1] = fmaf(w.y, xo, y[j4 * 4 + 1]);
            y[j4 * 4 + 2] = fmaf(w.z, xo, y[j4 * 4 + 2]);
            y[j4 * 4 + 3] = fmaf(w.w, xo, y[j4 * 4 + 3]);
        }
    }

    // LN over the 64 values — fully thread-local
    float s = 0.0f, q = 0.0f;
    #pragma unroll
    for (int j = 0; j < 64; j++) { s += y[j]; q = fmaf(y[j], y[j], q); }
    float mean = s * (1.0f / 64.0f);
    float var  = fmaf(-mean, mean, q * (1.0f / 64.0f));
    float r    = rsqrtf(var + 1e-5f);

    // permuted store: float2 l = { a[l], a[l+32] }
    float2* outp = (float2*)&g_ax[(size_t)item * 64];
    #pragma unroll
    for (int l = 0; l < 32; l++) {
        float a0 = fmaf((y[l]      - mean) * r, sgx[l],      sbxg[l]);
        float a1 = fmaf((y[l + 32] - mean) * r, sgx[l + 32], sbxg[l + 32]);
        outp[l] = make_float2(a0, a1);
    }
}

// ---------------------------------------------------------------------------
// Sequential LSTM scan. ONE warp = ONE batch row.
//   lane l (0..15):  gates i[l]   (ja=l)      and g[l]  (jb=l+32)
//   lane l (16..31): gates f[l-16](ja=l)      and o[l-16](jb=l+32)
// Full h vector is register-resident in every lane (broadcast via smem once
// per step) -> the 64x16 matvec is 32 local FMAs per lane, zero shuffles.
// c/h state + LN16 live on the upper 16 lanes.
// ---------------------------------------------------------------------------
__global__ void __launch_bounds__(32, 1) lstm_seq_kernel(
    const float* __restrict__ Wh,   const float* __restrict__ gh,
    const float* __restrict__ bh,   const float* __restrict__ gc,
    const float* __restrict__ bc,   const float* __restrict__ Wcls,
    const float* __restrict__ bcls, const float* __restrict__ h0,
    const float* __restrict__ c0,   float* __restrict__ out)
{
    const unsigned ALL = 0xffffffffu;
    const unsigned UPPER_MASK = 0xffff0000u;
    int lane  = threadIdx.x;
    int m     = lane & 15;
    bool upper = lane >= 16;
    int row   = blockIdx.x;

    __shared__ float sh[2][16];

    // per-lane gate rows ja = lane, jb = lane + 32
    float wa[16], wb[16];
    #pragma unroll
    for (int i = 0; i < 16; i++) {
        wa[i] = Wh[lane * 16 + i];
        wb[i] = Wh[(lane + 32) * 16 + i];
    }
    float gha = gh[lane], ghb = gh[lane + 32];
    float bha = bh[lane], bhb = bh[lane + 32];
    float gcm = gc[m],    bcm = bc[m];

    float h = 0.0f, c = 0.0f;
    if (upper) {
        h = h0[row * 16 + m];
        c = c0[row * 16 + m];
        sh[0][m] = h;
    }
    __syncwarp();

    const float2* ax = (const float2*)g_ax;
    int base = row * 32 + lane;              // float2 index for t=0
    const int stride = BATCH * 32;           // float2s per timestep
    float2 p0 = ax[base];
    float2 p1 = ax[base + stride];

    for (int t = 0; t < T_STEPS; t++) {
        // broadcast h: all lanes read the 16 floats (LDS.128 x4, broadcast)
        const float4* hb = (const float4*)sh[t & 1];
        float4 hv0 = hb[0], hv1 = hb[1], hv2 = hb[2], hv3 = hb[3];

        float2 cur = p0;
        p0 = p1;
        if (t + 2 < T_STEPS) p1 = ax[base + (t + 2) * stride];

        // matvec: 2 gate rows per lane, 4 independent chains for latency
        float ya0, ya1, yb0, yb1;
        ya0 = wa[0]*hv0.x; ya1 = wa[1]*hv0.y; yb0 = wb[0]*hv0.x; yb1 = wb[1]*hv0.y;
        ya0 = fmaf(wa[2],  hv0.z, ya0); ya1 = fmaf(wa[3],  hv0.w, ya1);
        yb0 = fmaf(wb[2],  hv0.z, yb0); yb1 = fmaf(wb[3],  hv0.w, yb1);
        ya0 = fmaf(wa[4],  hv1.x, ya0); ya1 = fmaf(wa[5],  hv1.y, ya1);
        yb0 = fmaf(wb[4],  hv1.x, yb0); yb1 = fmaf(wb[5],  hv1.y, yb1);
        ya0 = fmaf(wa[6],  hv1.z, ya0); ya1 = fmaf(wa[7],  hv1.w, ya1);
        yb0 = fmaf(wb[6],  hv1.z, yb0); yb1 = fmaf(wb[7],  hv1.w, yb1);
        ya0 = fmaf(wa[8],  hv2.x, ya0); ya1 = fmaf(wa[9],  hv2.y, ya1);
        yb0 = fmaf(wb[8],  hv2.x, yb0); yb1 = fmaf(wb[9],  hv2.y, yb1);
        ya0 = fmaf(wa[10], hv2.z, ya0); ya1 = fmaf(wa[11], hv2.w, ya1);
        yb0 = fmaf(wb[10], hv2.z, yb0); yb1 = fmaf(wb[11], hv2.w, yb1);
        ya0 = fmaf(wa[12], hv3.x, ya0); ya1 = fmaf(wa[13], hv3.y, ya1);
        yb0 = fmaf(wb[12], hv3.x, yb0); yb1 = fmaf(wb[13], hv3.y, yb1);
        ya0 = fmaf(wa[14], hv3.z, ya0); ya1 = fmaf(wa[15], hv3.w, ya1);
        yb0 = fmaf(wb[14], hv3.z, yb0); yb1 = fmaf(wb[15], hv3.w, yb1);
        float ya = ya0 + ya1;
        float yb = yb0 + yb1;

        // LN64 over all 32 lanes x 2 values
        float s = ya + yb;
        float q = fmaf(ya, ya, yb * yb);
        #pragma unroll
        for (int d = 1; d < 32; d <<= 1) {
            s += __shfl_xor_sync(ALL, s, d);
            q += __shfl_xor_sync(ALL, q, d);
        }
        float mean = s * (1.0f / 64.0f);
        float var  = fmaf(-mean, mean, q * (1.0f / 64.0f));
        float r    = rsqrtf(var + 1e-5f);

        float ga = fmaf((ya - mean) * r, gha, bha) + cur.x;  // i | f
        float gb = fmaf((yb - mean) * r, ghb, bhb) + cur.y;  // g | o

        float u1 = sigf(ga);                                  // sig(i) | sig(f)
        float arg2 = upper ? gb : (2.0f * gb);
        float u2 = sigf(arg2);                                // sig(o) | sig(2g)
        float Aval = u1 * fmaf(2.0f, u2, -1.0f);              // lower: sig(i)*tanh(g)
        float A = __shfl_xor_sync(ALL, Aval, 16);             // upper receives A

        if (upper) {
            c = fmaf(u1, c, A);
            // LN16 over the 16 c values (upper half only)
            float sc = c, qc = c * c;
            #pragma unroll
            for (int d = 1; d < 16; d <<= 1) {
                sc += __shfl_xor_sync(UPPER_MASK, sc, d);
                qc += __shfl_xor_sync(UPPER_MASK, qc, d);
            }
            float mc = sc * (1.0f / 16.0f);
            float vc = fmaf(-mc, mc, qc * (1.0f / 16.0f));
            float rc = rsqrtf(vc + 1e-5f);
            float cn = fmaf((c - mc) * rc, gcm, bcm);
            float th = fmaf(2.0f, sigf(2.0f * cn), -1.0f);    // tanh(cn)
            h = u2 * th;                                      // sig(o) * tanh(cn)
            sh[(t + 1) & 1][m] = h;
        }
        __syncwarp();
    }

    // classifier on upper lanes: sigmoid(h . W_cls + b_cls)
    if (upper) {
        float v = h * Wcls[m];
        #pragma unroll
        for (int d = 1; d < 16; d <<= 1)
            v += __shfl_xor_sync(UPPER_MASK, v, d);
        if (m == 0)
            out[row] = sigf(v + bcls[0]);
    }
}

// ---------------------------------------------------------------------------
extern "C" void kernel_launch(void* const* d_in, const int* in_sizes, int n_in,
                              void* d_out, int out_size)
{
    const float* x     = (const float*)d_in[0];
    const float* Wm    = (const float*)d_in[1];
    const float* bm    = (const float*)d_in[2];
    const float* Wc    = (const float*)d_in[3];
    const float* bconv = (const float*)d_in[4];
    const float* Wx    = (const float*)d_in[5];
    const float* Wh    = (const float*)d_in[6];
    const float* bg    = (const float*)d_in[7];
    const float* gx    = (const float*)d_in[8];
    const float* bx    = (const float*)d_in[9];
    const float* gh    = (const float*)d_in[10];
    const float* bh    = (const float*)d_in[11];
    const float* gc    = (const float*)d_in[12];
    const float* bc    = (const float*)d_in[13];
    const float* Wcls  = (const float*)d_in[14];
    const float* bcls  = (const float*)d_in[15];
    const float* h0    = (const float*)d_in[16];
    const float* c0    = (const float*)d_in[17];
    float* out = (float*)d_out;

    prepass_kernel<<<(T_STEPS * BATCH + 255) / 256, 256>>>(
        x, Wm, bm, Wc, bconv, Wx, gx, bx, bg);
    lstm_seq_kernel<<<BATCH, 32>>>(Wh, gh, bh, gc, bc, Wcls, bcls, h0, c0, out);
}